// round 16
// baseline (speedup 1.0000x reference)
#include <cuda_runtime.h>
#include <cstdint>
#include <math.h>

#define Bb 8
#define Nn 8192
#define Mm 512
#define Kk 6
#define NSs 16
#define Cc 13
#define Dd 64

// ---- output layout (float32, concatenated in reference return order) ----
#define OFF_FINAL_ASSO 0            // (B,N,K)   393216
#define OFF_CLUSTER_IDX 393216      // (B,M)     4096
#define OFF_C2P_IDX 397312          // (B,N,K)   393216
#define OFF_C2P_ABS 790528          // (B,N,K)   393216
#define OFF_OUT 1183744             // (B,N,C)   851968
#define OFF_REPXYZ 2035712          // (B,N,3)   196608
#define OFF_REPLABEL 2232320        // (B,N,C)   851968
#define OFF_FEADIST 3084288         // (B,N,K)   393216
#define OFF_PFEA 3477504            // (B,N,D)   4194304
#define OFF_SPLABT 7671808          // (B,C,M)   53248
#define OFF_PSEUDO 7725056          // (B,M)     4096
#define OFF_PSEUDO_OH 7729152       // (B,C,M)   53248

// ---- scratch ----
__device__ int   g_cluster_idx[Bb*Mm];
__device__ float g_cluster_xyz[Bb*Mm*3];
__device__ int   g_idx[Bb*Nn*Kk];          // c2p_idx_abs
__device__ float g_spfea[Bb*Mm*Dd];
__device__ float g_spxyz[Bb*Mm*3];
__device__ float g_sfw[Bb*Mm*16];          // sp_fea @ Wf1[l]
__device__ float g_sxw[Bb*Mm*16];          // sp_xyz @ Wx1[l]
__device__ float g_pm[4*Bb*Nn*16];
__device__ float g_pw[4*Bb*Nn*16];         // p_fea @ Wf1[l], all layers (precomputed)
__device__ float g_splabel[Bb*Mm*Cc];
__device__ int   g_counts[Bb*Mm];
__device__ int   g_offsets[Bb*Mm+1];
__device__ int   g_cursor[Bb*Mm];
__device__ int   g_csr[Bb*Nn*Kk];

// ---- f32x2 helpers (FFMA2 — not emitted by ptxas from C++) ----
__device__ __forceinline__ unsigned long long pack2(float lo, float hi) {
    unsigned long long r;
    asm("mov.b64 %0, {%1, %2};" : "=l"(r) : "f"(lo), "f"(hi));
    return r;
}
__device__ __forceinline__ void unpack2(unsigned long long v, float& lo, float& hi) {
    asm("mov.b64 {%0, %1}, %2;" : "=f"(lo), "=f"(hi) : "l"(v));
}
__device__ __forceinline__ unsigned long long fma2(unsigned long long a,
                                                   unsigned long long b,
                                                   unsigned long long c) {
    unsigned long long d;
    asm("fma.rn.f32x2 %0, %1, %2, %3;" : "=l"(d) : "l"(a), "l"(b), "l"(c));
    return d;
}
__device__ __forceinline__ unsigned redux_max_u32(unsigned v) {
    unsigned r;
    asm volatile("redux.sync.max.u32 %0, %1, 0xffffffff;" : "=r"(r) : "r"(v));
    return r;
}
__device__ __forceinline__ int redux_min_s32(int v) {
    int r;
    asm volatile("redux.sync.min.s32 %0, %1, 0xffffffff;" : "=r"(r) : "r"(v));
    return r;
}

// ---------------- FPS: one block per batch, register-resident points ----------------
__global__ void fps_kernel(const float* __restrict__ pc, float* __restrict__ out_cidx_f) {
    int b = blockIdx.x;
    extern __shared__ float sm[];
    float* sx = sm; float* sy = sm + Nn; float* sz = sm + 2*Nn;
    __shared__ unsigned rv[2][32];
    __shared__ int ri[2][32];
    int t = threadIdx.x;
    int lane = t & 31, wid = t >> 5;
    {
        int i = b*512 + (t & 511);
        if (t < 512) { g_counts[i] = 0; g_cursor[i] = 0; }
    }
    const float* base = pc + (size_t)b*Nn*6;
    for (int p = t; p < Nn; p += 1024) {
        sx[p] = base[(size_t)p*6+0];
        sy[p] = base[(size_t)p*6+1];
        sz[p] = base[(size_t)p*6+2];
    }
    __syncthreads();
    const int p0 = t * 8;
    float rx[8], ry[8], rz[8], dist[8];
#pragma unroll
    for (int j = 0; j < 8; j++) {
        rx[j] = sx[p0+j]; ry[j] = sy[p0+j]; rz[j] = sz[p0+j];
        dist[j] = 1e10f;
    }
    if (t == 0) {
        g_cluster_idx[b*Mm] = 0;
        out_cidx_f[b*Mm] = 0.0f;
        g_cluster_xyz[(b*Mm)*3+0] = sx[0];
        g_cluster_xyz[(b*Mm)*3+1] = sy[0];
        g_cluster_xyz[(b*Mm)*3+2] = sz[0];
    }
    int last = 0;
    for (int it = 1; it < Mm; it++) {
        float nlx = -sx[last], nly = -sy[last], nlz = -sz[last];
        float bv = -1e30f; int bi = 0x7FFFFFFF;
#pragma unroll
        for (int j = 0; j < 8; j++) {
            float dx = __fadd_rn(rx[j], nlx);
            float dy = __fadd_rn(ry[j], nly);
            float dz = __fadd_rn(rz[j], nlz);
            float d = __fadd_rn(__fadd_rn(__fmul_rn(dx,dx), __fmul_rn(dy,dy)), __fmul_rn(dz,dz));
            float nd = fminf(dist[j], d);
            dist[j] = nd;
            if (nd > bv) { bv = nd; bi = p0 + j; }   // ascending j -> first max kept
        }
        unsigned key = __float_as_uint(bv);        // nonneg -> order-preserving
        unsigned mx = redux_max_u32(key);
        int cand = (key == mx) ? bi : 0x7FFFFFFF;
        int wbi = redux_min_s32(cand);
        int par = it & 1;
        if (lane == 0) { rv[par][wid] = mx; ri[par][wid] = wbi; }
        __syncthreads();
        unsigned k2 = rv[par][lane];
        int i2 = ri[par][lane];
        unsigned gm = redux_max_u32(k2);
        int c2 = (k2 == gm) ? i2 : 0x7FFFFFFF;
        int win = redux_min_s32(c2);               // all warps compute same winner
        if (t == 0) {
            g_cluster_idx[b*Mm + it] = win;
            out_cidx_f[b*Mm + it] = (float)win;
            g_cluster_xyz[(b*Mm+it)*3+0] = sx[win];
            g_cluster_xyz[(b*Mm+it)*3+1] = sy[win];
            g_cluster_xyz[(b*Mm+it)*3+2] = sz[win];
        }
        last = win;
    }
}

// ---------------- top-K nearest clusters per point ----------------
__global__ void topk_kernel(const float* __restrict__ pc,
                            float* __restrict__ out_abs_f, float* __restrict__ out_c2p_f) {
    int b = blockIdx.y;
    int n = blockIdx.x*blockDim.x + threadIdx.x;
    __shared__ float cx[Mm], cy[Mm], cz[Mm];
    __shared__ int cid[Mm];
    for (int m = threadIdx.x; m < Mm; m += blockDim.x) {
        cx[m] = g_cluster_xyz[(b*Mm+m)*3+0];
        cy[m] = g_cluster_xyz[(b*Mm+m)*3+1];
        cz[m] = g_cluster_xyz[(b*Mm+m)*3+2];
        cid[m] = g_cluster_idx[b*Mm+m];
    }
    __syncthreads();
    size_t bn = (size_t)b*Nn + n;
    float x = pc[bn*6+0], y = pc[bn*6+1], z = pc[bn*6+2];
    float bd[Kk]; int bm[Kk];
#pragma unroll
    for (int k = 0; k < Kk; k++) { bd[k] = 1e30f; bm[k] = 0; }
    for (int m = 0; m < Mm; m++) {
        float dx = x - cx[m], dy = y - cy[m], dz = z - cz[m];
        float d = __fadd_rn(__fadd_rn(__fmul_rn(dx,dx), __fmul_rn(dy,dy)), __fmul_rn(dz,dz));
        if (d < bd[Kk-1]) {
            bd[Kk-1] = d; bm[Kk-1] = m;
#pragma unroll
            for (int j = Kk-1; j > 0; j--) {
                if (bd[j] < bd[j-1]) {
                    float tv = bd[j]; bd[j] = bd[j-1]; bd[j-1] = tv;
                    int ti = bm[j]; bm[j] = bm[j-1]; bm[j-1] = ti;
                }
            }
        }
    }
#pragma unroll
    for (int k = 0; k < Kk; k++) {
        g_idx[bn*Kk+k] = bm[k];
        out_abs_f[bn*Kk+k] = (float)bm[k];
        out_c2p_f[bn*Kk+k] = (float)cid[bm[k]];
        atomicAdd(&g_counts[b*Mm + bm[k]], 1);
    }
}

// ---------------- exclusive scan over B*M=4096 counts ----------------
__global__ void scan_kernel() {
    __shared__ int partial[1024];
    int t = threadIdx.x;
    int v[4]; int s = 0;
#pragma unroll
    for (int j = 0; j < 4; j++) { v[j] = g_counts[t*4+j]; s += v[j]; }
    partial[t] = s;
    __syncthreads();
    for (int off = 1; off < 1024; off <<= 1) {
        int x = (t >= off) ? partial[t-off] : 0;
        __syncthreads();
        partial[t] += x;
        __syncthreads();
    }
    int run = (t == 0) ? 0 : partial[t-1];
#pragma unroll
    for (int j = 0; j < 4; j++) { g_offsets[t*4+j] = run; run += v[j]; }
    if (t == 1023) g_offsets[Bb*Mm] = run;
}

__global__ void fill_kernel() {
    int id = blockIdx.x*blockDim.x + threadIdx.x;  // point id over B*N
    int b = id / Nn, n = id % Nn;
    size_t bn = (size_t)id;
#pragma unroll
    for (int k = 0; k < Kk; k++) {
        int m = g_idx[bn*Kk+k];
        int bmi = b*Mm + m;
        int pos = atomicAdd(&g_cursor[bmi], 1);
        g_csr[g_offsets[bmi] + pos] = n*Kk + k;
    }
}

// ---------------- p_fea + head + pm + pw MLPs (f32x2 packed) ----------------
// smem: Wk1[64] Wk2[2048] Wg[192] W1[4096] W2[832] Wm1[4096] Wm2[1024] Wf1[4096]
__global__ void pfea_kernel(const float* __restrict__ pc, const float* __restrict__ knn,
                            const float* __restrict__ Wk1, const float* __restrict__ Wk2,
                            const float* __restrict__ Wg,
                            const float* __restrict__ W1, const float* __restrict__ W2,
                            const float* __restrict__ Wm1, const float* __restrict__ Wm2,
                            const float* __restrict__ Wf1,
                            float* __restrict__ pfea_out, float* __restrict__ head_out) {
    extern __shared__ float smw[];
    float* sWk1 = smw;          // 64
    float* sWk2 = smw + 64;     // 2048
    float* sWg  = smw + 2112;   // 192
    float* sW1  = smw + 2304;   // 4096
    float* sW2  = smw + 6400;   // 832
    float* sWm1 = smw + 7232;   // 4096
    float* sWm2 = smw + 11328;  // 1024
    float* sWf1 = smw + 12352;  // 4096
    for (int i = threadIdx.x; i < 64;   i += blockDim.x) sWk1[i] = Wk1[i];
    for (int i = threadIdx.x; i < 2048; i += blockDim.x) sWk2[i] = Wk2[i];
    for (int i = threadIdx.x; i < 192;  i += blockDim.x) sWg[i]  = Wg[i];
    for (int i = threadIdx.x; i < 4096; i += blockDim.x) sW1[i]  = W1[i];
    for (int i = threadIdx.x; i < 832;  i += blockDim.x) sW2[i]  = W2[i];
    for (int i = threadIdx.x; i < 4096; i += blockDim.x) sWm1[i] = Wm1[i];
    for (int i = threadIdx.x; i < 1024; i += blockDim.x) sWm2[i] = Wm2[i];
    for (int i = threadIdx.x; i < 4096; i += blockDim.x) sWf1[i] = Wf1[i];
    __syncthreads();

    size_t bn = (size_t)(blockIdx.x*blockDim.x + threadIdx.x);
    const float* kp = knn + bn*NSs*2;

    float hk[Dd];
#pragma unroll
    for (int d = 0; d < Dd; d++) hk[d] = 0.0f;
    unsigned long long o2[32];
    for (int s = 0; s < NSs; s++) {
        float a = kp[s*2+0], b2 = kp[s*2+1];
#pragma unroll
        for (int q = 0; q < 32; q++) o2[q] = 0ULL;
        for (int j = 0; j < 32; j++) {
            float hj = fmaxf(a*sWk1[j] + b2*sWk1[32+j], 0.0f);
            unsigned long long hj2 = pack2(hj, hj);
            const unsigned long long* wrow = (const unsigned long long*)(sWk2 + j*64);
#pragma unroll
            for (int q = 0; q < 32; q++) o2[q] = fma2(hj2, wrow[q], o2[q]);
        }
#pragma unroll
        for (int q = 0; q < 32; q++) {
            float lo, hi; unpack2(o2[q], lo, hi);
            hk[2*q]   = fmaxf(hk[2*q],   fmaxf(lo, 0.0f));
            hk[2*q+1] = fmaxf(hk[2*q+1], fmaxf(hi, 0.0f));
        }
    }
    float f0 = pc[bn*6+3], f1 = pc[bn*6+4], f2 = pc[bn*6+5];
#pragma unroll
    for (int d = 0; d < Dd; d++) {
        float hg = fmaxf(f0*sWg[d] + f1*sWg[64+d] + f2*sWg[128+d], 0.0f);
        hk[d] = hk[d] + hg;               // hk now holds p_fea
        pfea_out[bn*Dd + d] = hk[d];
    }
    // head: relu(p@W1)@W2
#pragma unroll
    for (int q = 0; q < 32; q++) o2[q] = 0ULL;
    for (int d = 0; d < Dd; d++) {
        unsigned long long pd2 = pack2(hk[d], hk[d]);
        const unsigned long long* wrow = (const unsigned long long*)(sW1 + d*64);
#pragma unroll
        for (int q = 0; q < 32; q++) o2[q] = fma2(pd2, wrow[q], o2[q]);
    }
    float oc[Cc];
#pragma unroll
    for (int c = 0; c < Cc; c++) oc[c] = 0.0f;
#pragma unroll
    for (int q = 0; q < 32; q++) {
        float lo, hi; unpack2(o2[q], lo, hi);
        float h0 = fmaxf(lo, 0.0f), h1 = fmaxf(hi, 0.0f);
        const float* r0 = sW2 + (2*q)*Cc;
        const float* r1 = sW2 + (2*q+1)*Cc;
#pragma unroll
        for (int c = 0; c < Cc; c++) oc[c] += h0*r0[c] + h1*r1[c];
    }
#pragma unroll
    for (int c = 0; c < Cc; c++) head_out[bn*Cc + c] = oc[c];
    // pm + pw for all 4 layers
    for (int l = 0; l < 4; l++) {
        unsigned long long a2[8], pw2[8];
#pragma unroll
        for (int q = 0; q < 8; q++) { a2[q] = 0ULL; pw2[q] = 0ULL; }
        for (int d = 0; d < Dd; d++) {
            unsigned long long pd2 = pack2(hk[d], hk[d]);
            const unsigned long long* wrow = (const unsigned long long*)(sWm1 + l*1024 + d*16);
            const unsigned long long* frow = (const unsigned long long*)(sWf1 + l*1024 + d*16);
#pragma unroll
            for (int q = 0; q < 8; q++) {
                a2[q]  = fma2(pd2, wrow[q], a2[q]);
                pw2[q] = fma2(pd2, frow[q], pw2[q]);
            }
        }
        float* pwout = g_pw + ((size_t)l*Bb*Nn + bn)*16;
#pragma unroll
        for (int q = 0; q < 8; q++) {
            float lo, hi; unpack2(pw2[q], lo, hi);
            pwout[2*q] = lo; pwout[2*q+1] = hi;
        }
        float t16[16];
#pragma unroll
        for (int q = 0; q < 8; q++) {
            float lo, hi; unpack2(a2[q], lo, hi);
            t16[2*q] = fmaxf(lo, 0.0f); t16[2*q+1] = fmaxf(hi, 0.0f);
        }
        unsigned long long p2[8];
#pragma unroll
        for (int q = 0; q < 8; q++) p2[q] = 0ULL;
#pragma unroll
        for (int i = 0; i < 16; i++) {
            unsigned long long ti2 = pack2(t16[i], t16[i]);
            const unsigned long long* wrow = (const unsigned long long*)(sWm2 + l*256 + i*16);
#pragma unroll
            for (int q = 0; q < 8; q++) p2[q] = fma2(ti2, wrow[q], p2[q]);
        }
#pragma unroll
        for (int q = 0; q < 8; q++) {
            float lo, hi; unpack2(p2[q], lo, hi);
            g_pm[((size_t)l*Bb*Nn + bn)*16 + 2*q]   = fmaxf(lo, 0.0f);
            g_pm[((size_t)l*Bb*Nn + bn)*16 + 2*q+1] = fmaxf(hi, 0.0f);
        }
    }
}

// ---------------- scatter_weighted: 1 cluster/block, 8 warps/cluster ----------------
__global__ void scatter_kernel(const float* __restrict__ pfea, const float* __restrict__ pc,
                               const float* __restrict__ w, int init,
                               const float* __restrict__ Wf1, const float* __restrict__ Wx1,
                               int lnext) {
    __shared__ __align__(8) float sWf1[1024];
    __shared__ float sWx1[48];
    __shared__ float part[8][Dd];
    __shared__ float pden[8];
    __shared__ float pxyz[8][3];
    if (lnext >= 0) {
        for (int i = threadIdx.x; i < 1024; i += blockDim.x) sWf1[i] = Wf1[lnext*1024 + i];
        for (int i = threadIdx.x; i < 48;   i += blockDim.x) sWx1[i] = Wx1[lnext*48 + i];
    }
    __syncthreads();
    int wq = threadIdx.x >> 5;           // warp 0..7
    int lane = threadIdx.x & 31;
    int gw = blockIdx.x;
    int b = gw / Mm;
    int beg = g_offsets[gw], end = g_offsets[gw+1];
    float a0 = 0.f, a1 = 0.f, den = 0.f, axyz = 0.f;
    for (int e = beg + wq; e < end; e += 8) {
        int ent = g_csr[e];
        int n = ent / Kk, k = ent - (ent/Kk)*Kk;
        size_t bn = (size_t)b*Nn + n;
        float wt = init ? 1.0f : w[bn*Kk + k];
        const float* pf = pfea + bn*Dd;
        a0 += wt * pf[lane];
        a1 += wt * pf[lane+32];
        den += wt;
        if (lane < 3) axyz += wt * pc[bn*6 + lane];
    }
    part[wq][lane] = a0;
    part[wq][lane+32] = a1;
    if (lane == 0) pden[wq] = den;
    if (lane < 3) pxyz[wq][lane] = axyz;
    __syncthreads();
    if (wq == 0) {
        float a0s = 0.f, a1s = 0.f, dens = 0.f;
#pragma unroll
        for (int q = 0; q < 8; q++) {
            a0s += part[q][lane];
            a1s += part[q][lane+32];
            dens += pden[q];
        }
        float dd = init ? fmaxf(dens, 1.0f) : fmaxf(dens, 1e-8f);
        float v0 = a0s / dd, v1 = a1s / dd;
        g_spfea[(size_t)gw*Dd + lane]      = v0;
        g_spfea[(size_t)gw*Dd + 32 + lane] = v1;
        float xv = 0.f;
        if (lane < 3) {
            float xs = 0.f;
#pragma unroll
            for (int q = 0; q < 8; q++) xs += pxyz[q][lane];
            xv = init ? g_cluster_xyz[gw*3 + lane] : (xs / dd);
            g_spxyz[gw*3 + lane] = xv;
        }
        if (lnext < 0) return;
        part[0][lane] = v0;          // reuse as full spfea row
        part[0][lane+32] = v1;
        if (lane < 3) pxyz[0][lane] = xv;
        __syncwarp();
        if (lane < 16) {
            float accf = 0.f;
            const float* sv = part[0];
#pragma unroll
            for (int d = 0; d < Dd; d++) accf += sv[d] * sWf1[d*16 + lane];
            g_sfw[gw*16 + lane] = accf;
            float accx = pxyz[0][0]*sWx1[lane] + pxyz[0][1]*sWx1[16+lane]
                       + pxyz[0][2]*sWx1[32+lane];
            g_sxw[gw*16 + lane] = accx;
        }
    }
}

// ---------------- SLIC layer: logits + softmax (pw precomputed) ----------------
__global__ void layer_kernel(int l, const float* __restrict__ pc,
                             const float* __restrict__ Wf2,
                             const float* __restrict__ Wx1, const float* __restrict__ Wx2,
                             float* __restrict__ wout) {
    __shared__ __align__(8) float sf2[256];
    __shared__ float sx1[48];
    __shared__ __align__(8) float sx2[256];
    for (int i = threadIdx.x; i < 256;  i += blockDim.x) sf2[i] = Wf2[l*256 + i];
    for (int i = threadIdx.x; i < 48;   i += blockDim.x) sx1[i] = Wx1[l*48 + i];
    for (int i = threadIdx.x; i < 256;  i += blockDim.x) sx2[i] = Wx2[l*256 + i];
    __syncthreads();

    int id = blockIdx.x*blockDim.x + threadIdx.x;
    int b = id / Nn;
    size_t bn = (size_t)id;

    // pw precomputed in pfea_kernel
    float pw[16];
    {
        const float4* pw4 = (const float4*)(g_pw + ((size_t)l*Bb*Nn + bn)*16);
#pragma unroll
        for (int q = 0; q < 4; q++) {
            float4 v = pw4[q];
            pw[4*q] = v.x; pw[4*q+1] = v.y; pw[4*q+2] = v.z; pw[4*q+3] = v.w;
        }
    }

    float x = pc[bn*6+0], y = pc[bn*6+1], z = pc[bn*6+2];
    float xw[16];
#pragma unroll
    for (int j = 0; j < 16; j++) xw[j] = x*sx1[j] + y*sx1[16+j] + z*sx1[32+j];

    float pm[16];
#pragma unroll
    for (int j = 0; j < 16; j++) pm[j] = g_pm[((size_t)l*Bb*Nn + bn)*16 + j];

    float lg[Kk];
#pragma unroll
    for (int k = 0; k < Kk; k++) {
        int m = g_idx[bn*Kk+k];
        int bm = b*Mm + m;
        const float* sfw = g_sfw + (size_t)bm*16;
        const float* sxw = g_sxw + (size_t)bm*16;
        unsigned long long wf2a[8], wx2a[8];
#pragma unroll
        for (int q = 0; q < 8; q++) { wf2a[q] = 0ULL; wx2a[q] = 0ULL; }
#pragma unroll
        for (int i = 0; i < 16; i++) {
            float tf = fmaxf(sfw[i] - pw[i], 0.0f);
            float tx = fmaxf(sxw[i] - xw[i], 0.0f);
            unsigned long long tf2 = pack2(tf, tf);
            unsigned long long tx2 = pack2(tx, tx);
            const unsigned long long* rf = (const unsigned long long*)(sf2 + i*16);
            const unsigned long long* rx = (const unsigned long long*)(sx2 + i*16);
#pragma unroll
            for (int q = 0; q < 8; q++) {
                wf2a[q] = fma2(tf2, rf[q], wf2a[q]);
                wx2a[q] = fma2(tx2, rx[q], wx2a[q]);
            }
        }
        float s = 0.0f;
#pragma unroll
        for (int q = 0; q < 8; q++) {
            float flo, fhi, xlo, xhi;
            unpack2(wf2a[q], flo, fhi);
            unpack2(wx2a[q], xlo, xhi);
            s += fmaxf(flo,0.f)*fmaxf(xlo,0.f)*pm[2*q] + fmaxf(fhi,0.f)*fmaxf(xhi,0.f)*pm[2*q+1];
        }
        lg[k] = s;
    }
    float mx = lg[0];
#pragma unroll
    for (int k = 1; k < Kk; k++) mx = fmaxf(mx, lg[k]);
    float e[Kk]; float s = 0.0f;
#pragma unroll
    for (int k = 0; k < Kk; k++) { e[k] = expf(lg[k]-mx); s += e[k]; }
#pragma unroll
    for (int k = 0; k < Kk; k++) wout[bn*Kk+k] = e[k] / s;
}

// ---------------- sp_label scatter + pseudo label: 1 cluster/block, 8 warps ----------------
__global__ void final2_kernel(const float* __restrict__ wfinal, const float* __restrict__ onehot,
                              const int* __restrict__ label,
                              float* __restrict__ splabT_out, float* __restrict__ pseudo_out,
                              float* __restrict__ pseudo_oh_out) {
    __shared__ float pacc[8][Cc];
    __shared__ float pden[8];
    __shared__ int   pcnt[8][Cc];
    int wq = threadIdx.x >> 5;
    int lane = threadIdx.x & 31;
    int gw = blockIdx.x;
    int b = gw / Mm, m = gw % Mm;
    int beg = g_offsets[gw], end = g_offsets[gw+1];
    float acc = 0.f, den = 0.f;
    int cnt = 0;
    for (int e = beg + wq; e < end; e += 8) {
        int ent = g_csr[e];
        int n = ent / Kk, k = ent - (ent/Kk)*Kk;
        size_t bn = (size_t)b*Nn + n;
        float wt = wfinal[bn*Kk + k];
        den += wt;
        int lab = label[bn];
        if (lane < Cc) {
            acc += wt * onehot[bn*Cc + lane];
            cnt += (lab == lane) ? 1 : 0;
        }
    }
    if (lane < Cc) { pacc[wq][lane] = acc; pcnt[wq][lane] = cnt; }
    if (lane == 0) pden[wq] = den;
    __syncthreads();
    if (wq == 0) {
        float dens = 0.f;
#pragma unroll
        for (int q = 0; q < 8; q++) dens += pden[q];
        float dd = fmaxf(dens, 1e-8f);
        float accs = 0.f; int cnts = -1;
        if (lane < Cc) {
            accs = 0.f; cnts = 0;
#pragma unroll
            for (int q = 0; q < 8; q++) { accs += pacc[q][lane]; cnts += pcnt[q][lane]; }
            float val = accs / dd;
            g_splabel[gw*Cc + lane] = val;
            splabT_out[(size_t)b*Cc*Mm + lane*Mm + m] = val;
        }
        int v = cnts;
        int bi = lane;
        const unsigned mask = 0xffffffffu;
#pragma unroll
        for (int off = 16; off > 0; off >>= 1) {
            int ov = __shfl_down_sync(mask, v, off);
            int oi = __shfl_down_sync(mask, bi, off);
            if (ov > v || (ov == v && oi < bi)) { v = ov; bi = oi; }
        }
        int win = __shfl_sync(mask, bi, 0);
        if (lane == 0) pseudo_out[b*Mm + m] = (float)win;
        if (lane < Cc) pseudo_oh_out[(size_t)b*Cc*Mm + lane*Mm + m] = (lane == win) ? 1.0f : 0.0f;
    }
}

// ---------------- merged final: feadist copy, argmax/re_p_xyz, re_p_label ----------------
__global__ void final13_kernel(const float* __restrict__ wfinal,
                               float* __restrict__ feadist_out, float* __restrict__ repxyz_out,
                               float* __restrict__ replabel_out) {
    int id = blockIdx.x*blockDim.x + threadIdx.x;
    int b = id / Nn;
    size_t bn = (size_t)id;
    float wv[Kk];
#pragma unroll
    for (int k = 0; k < Kk; k++) { wv[k] = wfinal[bn*Kk+k]; feadist_out[bn*Kk+k] = wv[k]; }
    int bk = 0; float bv = wv[0];
#pragma unroll
    for (int k = 1; k < Kk; k++) if (wv[k] > bv) { bv = wv[k]; bk = k; }
    int msel = g_idx[bn*Kk+bk];
#pragma unroll
    for (int j = 0; j < 3; j++) repxyz_out[bn*3+j] = g_spxyz[((size_t)b*Mm+msel)*3 + j];
    float acc[Cc];
#pragma unroll
    for (int c = 0; c < Cc; c++) acc[c] = 0.0f;
#pragma unroll
    for (int k = 0; k < Kk; k++) {
        float wt = wv[k];
        int m = g_idx[bn*Kk+k];
        const float* sl = g_splabel + ((size_t)b*Mm+m)*Cc;
#pragma unroll
        for (int c = 0; c < Cc; c++) acc[c] += wt * sl[c];
    }
#pragma unroll
    for (int c = 0; c < Cc; c++) replabel_out[bn*Cc+c] = acc[c];
}

extern "C" void kernel_launch(void* const* d_in, const int* in_sizes, int n_in,
                              void* d_out, int out_size) {
    const float* pc     = (const float*)d_in[0];
    const float* knn    = (const float*)d_in[1];
    const float* onehot = (const float*)d_in[2];
    const int*   label  = (const int*)d_in[3];
    const float* Wk1 = (const float*)d_in[4];
    const float* Wk2 = (const float*)d_in[5];
    const float* Wg  = (const float*)d_in[6];
    const float* W1  = (const float*)d_in[7];
    const float* W2  = (const float*)d_in[8];
    const float* Wf1 = (const float*)d_in[9];
    const float* Wf2 = (const float*)d_in[10];
    const float* Wx1 = (const float*)d_in[11];
    const float* Wx2 = (const float*)d_in[12];
    const float* Wm1 = (const float*)d_in[13];
    const float* Wm2 = (const float*)d_in[14];
    float* out = (float*)d_out;

    cudaFuncSetAttribute((const void*)fps_kernel,
                         cudaFuncAttributeMaxDynamicSharedMemorySize, 3*Nn*4);
    cudaFuncSetAttribute((const void*)pfea_kernel,
                         cudaFuncAttributeMaxDynamicSharedMemorySize, 16448*4);

    float* w_buf = out + OFF_FINAL_ASSO;   // final_asso region doubles as the live w buffer
    float* pfea  = out + OFF_PFEA;         // p_fea region is the canonical p_fea storage

    // Fork s2 off the capture stream FIRST (wait-event on an origin-stream event
    // is the required entry into the capture graph), then pfea runs on s2 with
    // no dependency on fps — concurrent at replay.
    cudaStream_t s2;
    cudaStreamCreateWithFlags(&s2, cudaStreamNonBlocking);
    cudaEvent_t e0, e2;
    cudaEventCreateWithFlags(&e0, cudaEventDisableTiming);
    cudaEventCreateWithFlags(&e2, cudaEventDisableTiming);

    cudaEventRecord(e0, 0);
    cudaStreamWaitEvent(s2, e0, 0);
    pfea_kernel<<<(Bb*Nn)/128, 128, 16448*4, s2>>>(pc, knn, Wk1, Wk2, Wg, W1, W2, Wm1, Wm2,
                                                   Wf1, pfea, out + OFF_OUT);
    cudaEventRecord(e2, s2);

    fps_kernel<<<Bb, 1024, 3*Nn*4>>>(pc, out + OFF_CLUSTER_IDX);        // zeroes counts too
    topk_kernel<<<dim3(Nn/256, Bb), 256>>>(pc, out + OFF_C2P_ABS, out + OFF_C2P_IDX);
    scan_kernel<<<1, 1024>>>();
    fill_kernel<<<(Bb*Nn)/256, 256>>>();
    cudaStreamWaitEvent(0, e2, 0);   // scatter needs pfea
    scatter_kernel<<<Bb*Mm, 256>>>(pfea, pc, w_buf, 1, Wf1, Wx1, 0);
    for (int l = 0; l < 4; l++) {
        layer_kernel<<<(Bb*Nn)/256, 256>>>(l, pc, Wf2, Wx1, Wx2, w_buf);
        scatter_kernel<<<Bb*Mm, 256>>>(pfea, pc, w_buf, 0, Wf1, Wx1,
                                       (l < 3) ? (l + 1) : -1);
    }
    final2_kernel<<<Bb*Mm, 256>>>(w_buf, onehot, label,
                                  out + OFF_SPLABT, out + OFF_PSEUDO, out + OFF_PSEUDO_OH);
    final13_kernel<<<(Bb*Nn)/256, 256>>>(w_buf, out + OFF_FEADIST, out + OFF_REPXYZ,
                                         out + OFF_REPLABEL);
}

// round 17
// speedup vs baseline: 1.0710x; 1.0710x over previous
#include <cuda_runtime.h>
#include <cstdint>
#include <math.h>

#define Bb 8
#define Nn 8192
#define Mm 512
#define Kk 6
#define NSs 16
#define Cc 13
#define Dd 64

// ---- output layout (float32, concatenated in reference return order) ----
#define OFF_FINAL_ASSO 0            // (B,N,K)   393216
#define OFF_CLUSTER_IDX 393216      // (B,M)     4096
#define OFF_C2P_IDX 397312          // (B,N,K)   393216
#define OFF_C2P_ABS 790528          // (B,N,K)   393216
#define OFF_OUT 1183744             // (B,N,C)   851968
#define OFF_REPXYZ 2035712          // (B,N,3)   196608
#define OFF_REPLABEL 2232320        // (B,N,C)   851968
#define OFF_FEADIST 3084288         // (B,N,K)   393216
#define OFF_PFEA 3477504            // (B,N,D)   4194304
#define OFF_SPLABT 7671808          // (B,C,M)   53248
#define OFF_PSEUDO 7725056          // (B,M)     4096
#define OFF_PSEUDO_OH 7729152       // (B,C,M)   53248

// ---- scratch ----
__device__ int   g_cluster_idx[Bb*Mm];
__device__ float g_cluster_xyz[Bb*Mm*3];
__device__ int   g_idx[Bb*Nn*Kk];          // c2p_idx_abs
__device__ float g_spxyz[Bb*Mm*3];         // written by LAST scatter only (read by final13)
__device__ float g_sfw[Bb*Mm*16];          // sp_fea @ Wf1[l]
__device__ float g_sxw[Bb*Mm*16];          // sp_xyz @ Wx1[l]
__device__ float g_pm[4*Bb*Nn*16];
__device__ float g_splabel[Bb*Mm*Cc];
__device__ int   g_counts[Bb*Mm];
__device__ int   g_offsets[Bb*Mm+1];
__device__ int   g_cursor[Bb*Mm];
__device__ int   g_csr[Bb*Nn*Kk];

// ---- f32x2 helpers (FFMA2 — not emitted by ptxas from C++) ----
__device__ __forceinline__ unsigned long long pack2(float lo, float hi) {
    unsigned long long r;
    asm("mov.b64 %0, {%1, %2};" : "=l"(r) : "f"(lo), "f"(hi));
    return r;
}
__device__ __forceinline__ void unpack2(unsigned long long v, float& lo, float& hi) {
    asm("mov.b64 {%0, %1}, %2;" : "=f"(lo), "=f"(hi) : "l"(v));
}
__device__ __forceinline__ unsigned long long fma2(unsigned long long a,
                                                   unsigned long long b,
                                                   unsigned long long c) {
    unsigned long long d;
    asm("fma.rn.f32x2 %0, %1, %2, %3;" : "=l"(d) : "l"(a), "l"(b), "l"(c));
    return d;
}
__device__ __forceinline__ unsigned redux_max_u32(unsigned v) {
    unsigned r;
    asm volatile("redux.sync.max.u32 %0, %1, 0xffffffff;" : "=r"(r) : "r"(v));
    return r;
}
__device__ __forceinline__ int redux_min_s32(int v) {
    int r;
    asm volatile("redux.sync.min.s32 %0, %1, 0xffffffff;" : "=r"(r) : "r"(v));
    return r;
}

// ---------------- FPS: one block per batch, register-resident points ----------------
__global__ void fps_kernel(const float* __restrict__ pc, float* __restrict__ out_cidx_f) {
    int b = blockIdx.x;
    extern __shared__ float sm[];
    float* sx = sm; float* sy = sm + Nn; float* sz = sm + 2*Nn;
    __shared__ unsigned rv[2][32];
    __shared__ int ri[2][32];
    int t = threadIdx.x;
    int lane = t & 31, wid = t >> 5;
    {
        int i = b*512 + (t & 511);
        if (t < 512) { g_counts[i] = 0; g_cursor[i] = 0; }
    }
    const float* base = pc + (size_t)b*Nn*6;
    for (int p = t; p < Nn; p += 1024) {
        sx[p] = base[(size_t)p*6+0];
        sy[p] = base[(size_t)p*6+1];
        sz[p] = base[(size_t)p*6+2];
    }
    __syncthreads();
    const int p0 = t * 8;
    float rx[8], ry[8], rz[8], dist[8];
#pragma unroll
    for (int j = 0; j < 8; j++) {
        rx[j] = sx[p0+j]; ry[j] = sy[p0+j]; rz[j] = sz[p0+j];
        dist[j] = 1e10f;
    }
    if (t == 0) {
        g_cluster_idx[b*Mm] = 0;
        out_cidx_f[b*Mm] = 0.0f;
        g_cluster_xyz[(b*Mm)*3+0] = sx[0];
        g_cluster_xyz[(b*Mm)*3+1] = sy[0];
        g_cluster_xyz[(b*Mm)*3+2] = sz[0];
    }
    int last = 0;
    for (int it = 1; it < Mm; it++) {
        float nlx = -sx[last], nly = -sy[last], nlz = -sz[last];
        float bv = -1e30f; int bi = 0x7FFFFFFF;
#pragma unroll
        for (int j = 0; j < 8; j++) {
            float dx = __fadd_rn(rx[j], nlx);
            float dy = __fadd_rn(ry[j], nly);
            float dz = __fadd_rn(rz[j], nlz);
            float d = __fadd_rn(__fadd_rn(__fmul_rn(dx,dx), __fmul_rn(dy,dy)), __fmul_rn(dz,dz));
            float nd = fminf(dist[j], d);
            dist[j] = nd;
            if (nd > bv) { bv = nd; bi = p0 + j; }   // ascending j -> first max kept
        }
        unsigned key = __float_as_uint(bv);        // nonneg -> order-preserving
        unsigned mx = redux_max_u32(key);
        int cand = (key == mx) ? bi : 0x7FFFFFFF;
        int wbi = redux_min_s32(cand);
        int par = it & 1;
        if (lane == 0) { rv[par][wid] = mx; ri[par][wid] = wbi; }
        __syncthreads();
        unsigned k2 = rv[par][lane];
        int i2 = ri[par][lane];
        unsigned gm = redux_max_u32(k2);
        int c2 = (k2 == gm) ? i2 : 0x7FFFFFFF;
        int win = redux_min_s32(c2);               // all warps compute same winner
        if (t == 0) {
            g_cluster_idx[b*Mm + it] = win;
            out_cidx_f[b*Mm + it] = (float)win;
            g_cluster_xyz[(b*Mm+it)*3+0] = sx[win];
            g_cluster_xyz[(b*Mm+it)*3+1] = sy[win];
            g_cluster_xyz[(b*Mm+it)*3+2] = sz[win];
        }
        last = win;
    }
}

// ---------------- top-K nearest clusters per point ----------------
__global__ void topk_kernel(const float* __restrict__ pc,
                            float* __restrict__ out_abs_f, float* __restrict__ out_c2p_f) {
    int b = blockIdx.y;
    int n = blockIdx.x*blockDim.x + threadIdx.x;
    __shared__ float cx[Mm], cy[Mm], cz[Mm];
    __shared__ int cid[Mm];
    for (int m = threadIdx.x; m < Mm; m += blockDim.x) {
        cx[m] = g_cluster_xyz[(b*Mm+m)*3+0];
        cy[m] = g_cluster_xyz[(b*Mm+m)*3+1];
        cz[m] = g_cluster_xyz[(b*Mm+m)*3+2];
        cid[m] = g_cluster_idx[b*Mm+m];
    }
    __syncthreads();
    size_t bn = (size_t)b*Nn + n;
    float x = pc[bn*6+0], y = pc[bn*6+1], z = pc[bn*6+2];
    float bd[Kk]; int bm[Kk];
#pragma unroll
    for (int k = 0; k < Kk; k++) { bd[k] = 1e30f; bm[k] = 0; }
    for (int m = 0; m < Mm; m++) {
        float dx = x - cx[m], dy = y - cy[m], dz = z - cz[m];
        float d = __fadd_rn(__fadd_rn(__fmul_rn(dx,dx), __fmul_rn(dy,dy)), __fmul_rn(dz,dz));
        if (d < bd[Kk-1]) {
            bd[Kk-1] = d; bm[Kk-1] = m;
#pragma unroll
            for (int j = Kk-1; j > 0; j--) {
                if (bd[j] < bd[j-1]) {
                    float tv = bd[j]; bd[j] = bd[j-1]; bd[j-1] = tv;
                    int ti = bm[j]; bm[j] = bm[j-1]; bm[j-1] = ti;
                }
            }
        }
    }
#pragma unroll
    for (int k = 0; k < Kk; k++) {
        g_idx[bn*Kk+k] = bm[k];
        out_abs_f[bn*Kk+k] = (float)bm[k];
        out_c2p_f[bn*Kk+k] = (float)cid[bm[k]];
        atomicAdd(&g_counts[b*Mm + bm[k]], 1);
    }
}

// ---------------- exclusive scan over B*M=4096 counts ----------------
__global__ void scan_kernel() {
    __shared__ int partial[1024];
    int t = threadIdx.x;
    int v[4]; int s = 0;
#pragma unroll
    for (int j = 0; j < 4; j++) { v[j] = g_counts[t*4+j]; s += v[j]; }
    partial[t] = s;
    __syncthreads();
    for (int off = 1; off < 1024; off <<= 1) {
        int x = (t >= off) ? partial[t-off] : 0;
        __syncthreads();
        partial[t] += x;
        __syncthreads();
    }
    int run = (t == 0) ? 0 : partial[t-1];
#pragma unroll
    for (int j = 0; j < 4; j++) { g_offsets[t*4+j] = run; run += v[j]; }
    if (t == 1023) g_offsets[Bb*Mm] = run;
}

__global__ void fill_kernel() {
    int id = blockIdx.x*blockDim.x + threadIdx.x;  // point id over B*N
    int b = id / Nn, n = id % Nn;
    size_t bn = (size_t)id;
#pragma unroll
    for (int k = 0; k < Kk; k++) {
        int m = g_idx[bn*Kk+k];
        int bmi = b*Mm + m;
        int pos = atomicAdd(&g_cursor[bmi], 1);
        g_csr[g_offsets[bmi] + pos] = n*Kk + k;
    }
}

// ---------------- p_fea + head + pm MLPs (f32x2 packed) ----------------
__global__ void pfea_kernel(const float* __restrict__ pc, const float* __restrict__ knn,
                            const float* __restrict__ Wk1, const float* __restrict__ Wk2,
                            const float* __restrict__ Wg,
                            const float* __restrict__ W1, const float* __restrict__ W2,
                            const float* __restrict__ Wm1, const float* __restrict__ Wm2,
                            float* __restrict__ pfea_out, float* __restrict__ head_out) {
    extern __shared__ float smw[];
    float* sWk1 = smw;          // 64
    float* sWk2 = smw + 64;     // 2048
    float* sWg  = smw + 2112;   // 192
    float* sW1  = smw + 2304;   // 4096
    float* sW2  = smw + 6400;   // 832
    float* sWm1 = smw + 7232;   // 4096
    float* sWm2 = smw + 11328;  // 1024
    for (int i = threadIdx.x; i < 64;   i += blockDim.x) sWk1[i] = Wk1[i];
    for (int i = threadIdx.x; i < 2048; i += blockDim.x) sWk2[i] = Wk2[i];
    for (int i = threadIdx.x; i < 192;  i += blockDim.x) sWg[i]  = Wg[i];
    for (int i = threadIdx.x; i < 4096; i += blockDim.x) sW1[i]  = W1[i];
    for (int i = threadIdx.x; i < 832;  i += blockDim.x) sW2[i]  = W2[i];
    for (int i = threadIdx.x; i < 4096; i += blockDim.x) sWm1[i] = Wm1[i];
    for (int i = threadIdx.x; i < 1024; i += blockDim.x) sWm2[i] = Wm2[i];
    __syncthreads();

    size_t bn = (size_t)(blockIdx.x*blockDim.x + threadIdx.x);
    const float* kp = knn + bn*NSs*2;

    float hk[Dd];
#pragma unroll
    for (int d = 0; d < Dd; d++) hk[d] = 0.0f;
    unsigned long long o2[32];
    for (int s = 0; s < NSs; s++) {
        float a = kp[s*2+0], b2 = kp[s*2+1];
#pragma unroll
        for (int q = 0; q < 32; q++) o2[q] = 0ULL;
        for (int j = 0; j < 32; j++) {
            float hj = fmaxf(a*sWk1[j] + b2*sWk1[32+j], 0.0f);
            unsigned long long hj2 = pack2(hj, hj);
            const unsigned long long* wrow = (const unsigned long long*)(sWk2 + j*64);
#pragma unroll
            for (int q = 0; q < 32; q++) o2[q] = fma2(hj2, wrow[q], o2[q]);
        }
#pragma unroll
        for (int q = 0; q < 32; q++) {
            float lo, hi; unpack2(o2[q], lo, hi);
            hk[2*q]   = fmaxf(hk[2*q],   fmaxf(lo, 0.0f));
            hk[2*q+1] = fmaxf(hk[2*q+1], fmaxf(hi, 0.0f));
        }
    }
    float f0 = pc[bn*6+3], f1 = pc[bn*6+4], f2 = pc[bn*6+5];
#pragma unroll
    for (int d = 0; d < Dd; d++) {
        float hg = fmaxf(f0*sWg[d] + f1*sWg[64+d] + f2*sWg[128+d], 0.0f);
        hk[d] = hk[d] + hg;               // hk now holds p_fea
        pfea_out[bn*Dd + d] = hk[d];
    }
    // head: relu(p@W1)@W2
#pragma unroll
    for (int q = 0; q < 32; q++) o2[q] = 0ULL;
    for (int d = 0; d < Dd; d++) {
        unsigned long long pd2 = pack2(hk[d], hk[d]);
        const unsigned long long* wrow = (const unsigned long long*)(sW1 + d*64);
#pragma unroll
        for (int q = 0; q < 32; q++) o2[q] = fma2(pd2, wrow[q], o2[q]);
    }
    float oc[Cc];
#pragma unroll
    for (int c = 0; c < Cc; c++) oc[c] = 0.0f;
#pragma unroll
    for (int q = 0; q < 32; q++) {
        float lo, hi; unpack2(o2[q], lo, hi);
        float h0 = fmaxf(lo, 0.0f), h1 = fmaxf(hi, 0.0f);
        const float* r0 = sW2 + (2*q)*Cc;
        const float* r1 = sW2 + (2*q+1)*Cc;
#pragma unroll
        for (int c = 0; c < Cc; c++) oc[c] += h0*r0[c] + h1*r1[c];
    }
#pragma unroll
    for (int c = 0; c < Cc; c++) head_out[bn*Cc + c] = oc[c];
    // pm for all 4 layers
    for (int l = 0; l < 4; l++) {
        unsigned long long a2[8];
#pragma unroll
        for (int q = 0; q < 8; q++) a2[q] = 0ULL;
        for (int d = 0; d < Dd; d++) {
            unsigned long long pd2 = pack2(hk[d], hk[d]);
            const unsigned long long* wrow = (const unsigned long long*)(sWm1 + l*1024 + d*16);
#pragma unroll
            for (int q = 0; q < 8; q++) a2[q] = fma2(pd2, wrow[q], a2[q]);
        }
        float t16[16];
#pragma unroll
        for (int q = 0; q < 8; q++) {
            float lo, hi; unpack2(a2[q], lo, hi);
            t16[2*q] = fmaxf(lo, 0.0f); t16[2*q+1] = fmaxf(hi, 0.0f);
        }
        unsigned long long p2[8];
#pragma unroll
        for (int q = 0; q < 8; q++) p2[q] = 0ULL;
#pragma unroll
        for (int i = 0; i < 16; i++) {
            unsigned long long ti2 = pack2(t16[i], t16[i]);
            const unsigned long long* wrow = (const unsigned long long*)(sWm2 + l*256 + i*16);
#pragma unroll
            for (int q = 0; q < 8; q++) p2[q] = fma2(ti2, wrow[q], p2[q]);
        }
#pragma unroll
        for (int q = 0; q < 8; q++) {
            float lo, hi; unpack2(p2[q], lo, hi);
            g_pm[((size_t)l*Bb*Nn + bn)*16 + 2*q]   = fmaxf(lo, 0.0f);
            g_pm[((size_t)l*Bb*Nn + bn)*16 + 2*q+1] = fmaxf(hi, 0.0f);
        }
    }
}

// ---------------- scatter_weighted: 1 cluster/block, 8 warps/cluster ----------------
// g_spfea is never read -> not stored; g_spxyz only read by final13 -> stored on last pass only
__global__ void scatter_kernel(const float* __restrict__ pfea, const float* __restrict__ pc,
                               const float* __restrict__ w, int init,
                               const float* __restrict__ Wf1, const float* __restrict__ Wx1,
                               int lnext) {
    __shared__ __align__(8) float sWf1[1024];
    __shared__ float sWx1[48];
    __shared__ float part[8][Dd];
    __shared__ float pden[8];
    __shared__ float pxyz[8][3];
    if (lnext >= 0) {
        for (int i = threadIdx.x; i < 1024; i += blockDim.x) sWf1[i] = Wf1[lnext*1024 + i];
        for (int i = threadIdx.x; i < 48;   i += blockDim.x) sWx1[i] = Wx1[lnext*48 + i];
    }
    __syncthreads();
    int wq = threadIdx.x >> 5;           // warp 0..7
    int lane = threadIdx.x & 31;
    int gw = blockIdx.x;
    int b = gw / Mm;
    int beg = g_offsets[gw], end = g_offsets[gw+1];
    float a0 = 0.f, a1 = 0.f, den = 0.f, axyz = 0.f;
    for (int e = beg + wq; e < end; e += 8) {
        int ent = g_csr[e];
        int n = ent / Kk, k = ent - (ent/Kk)*Kk;
        size_t bn = (size_t)b*Nn + n;
        float wt = init ? 1.0f : w[bn*Kk + k];
        const float* pf = pfea + bn*Dd;
        a0 += wt * pf[lane];
        a1 += wt * pf[lane+32];
        den += wt;
        if (lane < 3) axyz += wt * pc[bn*6 + lane];
    }
    part[wq][lane] = a0;
    part[wq][lane+32] = a1;
    if (lane == 0) pden[wq] = den;
    if (lane < 3) pxyz[wq][lane] = axyz;
    __syncthreads();
    if (wq == 0) {
        float a0s = 0.f, a1s = 0.f, dens = 0.f;
#pragma unroll
        for (int q = 0; q < 8; q++) {
            a0s += part[q][lane];
            a1s += part[q][lane+32];
            dens += pden[q];
        }
        float dd = init ? fmaxf(dens, 1.0f) : fmaxf(dens, 1e-8f);
        float v0 = a0s / dd, v1 = a1s / dd;
        float xv = 0.f;
        if (lane < 3) {
            float xs = 0.f;
#pragma unroll
            for (int q = 0; q < 8; q++) xs += pxyz[q][lane];
            xv = init ? g_cluster_xyz[gw*3 + lane] : (xs / dd);
            if (lnext < 0) g_spxyz[gw*3 + lane] = xv;   // only the final pass is consumed
        }
        if (lnext < 0) return;
        part[0][lane] = v0;          // reuse as full spfea row
        part[0][lane+32] = v1;
        if (lane < 3) pxyz[0][lane] = xv;
        __syncwarp();
        if (lane < 16) {
            float accf = 0.f;
            const float* sv = part[0];
#pragma unroll
            for (int d = 0; d < Dd; d++) accf += sv[d] * sWf1[d*16 + lane];
            g_sfw[gw*16 + lane] = accf;
            float accx = pxyz[0][0]*sWx1[lane] + pxyz[0][1]*sWx1[16+lane]
                       + pxyz[0][2]*sWx1[32+lane];
            g_sxw[gw*16 + lane] = accx;
        }
    }
}

// ---------------- SLIC layer: logits + softmax (factored MLP1, float4 p loads) ----------------
__global__ void layer_kernel(int l, const float* __restrict__ pfea, const float* __restrict__ pc,
                             const float* __restrict__ Wf1, const float* __restrict__ Wf2,
                             const float* __restrict__ Wx1, const float* __restrict__ Wx2,
                             float* __restrict__ wout) {
    __shared__ __align__(8) float sf1[1024];
    __shared__ __align__(8) float sf2[256];
    __shared__ float sx1[48];
    __shared__ __align__(8) float sx2[256];
    for (int i = threadIdx.x; i < 1024; i += blockDim.x) sf1[i] = Wf1[l*1024 + i];
    for (int i = threadIdx.x; i < 256;  i += blockDim.x) sf2[i] = Wf2[l*256 + i];
    for (int i = threadIdx.x; i < 48;   i += blockDim.x) sx1[i] = Wx1[l*48 + i];
    for (int i = threadIdx.x; i < 256;  i += blockDim.x) sx2[i] = Wx2[l*256 + i];
    __syncthreads();

    int id = blockIdx.x*blockDim.x + threadIdx.x;
    int b = id / Nn;
    size_t bn = (size_t)id;

    // pW = p_fea @ Wf1[l]  (float4 loads of the p row)
    unsigned long long pw2[8];
#pragma unroll
    for (int q = 0; q < 8; q++) pw2[q] = 0ULL;
    const float4* p4 = (const float4*)(pfea + bn*Dd);
    for (int d4 = 0; d4 < Dd/4; d4++) {
        float4 pv = p4[d4];
        float pe[4] = {pv.x, pv.y, pv.z, pv.w};
#pragma unroll
        for (int r = 0; r < 4; r++) {
            unsigned long long pd2 = pack2(pe[r], pe[r]);
            const unsigned long long* wrow = (const unsigned long long*)(sf1 + (d4*4+r)*16);
#pragma unroll
            for (int q = 0; q < 8; q++) pw2[q] = fma2(pd2, wrow[q], pw2[q]);
        }
    }
    float pw[16];
#pragma unroll
    for (int q = 0; q < 8; q++) unpack2(pw2[q], pw[2*q], pw[2*q+1]);

    float x = pc[bn*6+0], y = pc[bn*6+1], z = pc[bn*6+2];
    float xw[16];
#pragma unroll
    for (int j = 0; j < 16; j++) xw[j] = x*sx1[j] + y*sx1[16+j] + z*sx1[32+j];

    float pm[16];
#pragma unroll
    for (int j = 0; j < 16; j++) pm[j] = g_pm[((size_t)l*Bb*Nn + bn)*16 + j];

    float lg[Kk];
#pragma unroll
    for (int k = 0; k < Kk; k++) {
        int m = g_idx[bn*Kk+k];
        int bm = b*Mm + m;
        const float* sfw = g_sfw + (size_t)bm*16;
        const float* sxw = g_sxw + (size_t)bm*16;
        unsigned long long wf2a[8], wx2a[8];
#pragma unroll
        for (int q = 0; q < 8; q++) { wf2a[q] = 0ULL; wx2a[q] = 0ULL; }
#pragma unroll
        for (int i = 0; i < 16; i++) {
            float tf = fmaxf(sfw[i] - pw[i], 0.0f);
            float tx = fmaxf(sxw[i] - xw[i], 0.0f);
            unsigned long long tf2 = pack2(tf, tf);
            unsigned long long tx2 = pack2(tx, tx);
            const unsigned long long* rf = (const unsigned long long*)(sf2 + i*16);
            const unsigned long long* rx = (const unsigned long long*)(sx2 + i*16);
#pragma unroll
            for (int q = 0; q < 8; q++) {
                wf2a[q] = fma2(tf2, rf[q], wf2a[q]);
                wx2a[q] = fma2(tx2, rx[q], wx2a[q]);
            }
        }
        float s = 0.0f;
#pragma unroll
        for (int q = 0; q < 8; q++) {
            float flo, fhi, xlo, xhi;
            unpack2(wf2a[q], flo, fhi);
            unpack2(wx2a[q], xlo, xhi);
            s += fmaxf(flo,0.f)*fmaxf(xlo,0.f)*pm[2*q] + fmaxf(fhi,0.f)*fmaxf(xhi,0.f)*pm[2*q+1];
        }
        lg[k] = s;
    }
    float mx = lg[0];
#pragma unroll
    for (int k = 1; k < Kk; k++) mx = fmaxf(mx, lg[k]);
    float e[Kk]; float s = 0.0f;
#pragma unroll
    for (int k = 0; k < Kk; k++) { e[k] = expf(lg[k]-mx); s += e[k]; }
#pragma unroll
    for (int k = 0; k < Kk; k++) wout[bn*Kk+k] = e[k] / s;
}

// ---------------- sp_label scatter + pseudo label: 1 cluster/block, 8 warps ----------------
__global__ void final2_kernel(const float* __restrict__ wfinal, const float* __restrict__ onehot,
                              const int* __restrict__ label,
                              float* __restrict__ splabT_out, float* __restrict__ pseudo_out,
                              float* __restrict__ pseudo_oh_out) {
    __shared__ float pacc[8][Cc];
    __shared__ float pden[8];
    __shared__ int   pcnt[8][Cc];
    int wq = threadIdx.x >> 5;
    int lane = threadIdx.x & 31;
    int gw = blockIdx.x;
    int b = gw / Mm, m = gw % Mm;
    int beg = g_offsets[gw], end = g_offsets[gw+1];
    float acc = 0.f, den = 0.f;
    int cnt = 0;
    for (int e = beg + wq; e < end; e += 8) {
        int ent = g_csr[e];
        int n = ent / Kk, k = ent - (ent/Kk)*Kk;
        size_t bn = (size_t)b*Nn + n;
        float wt = wfinal[bn*Kk + k];
        den += wt;
        int lab = label[bn];
        if (lane < Cc) {
            acc += wt * onehot[bn*Cc + lane];
            cnt += (lab == lane) ? 1 : 0;
        }
    }
    if (lane < Cc) { pacc[wq][lane] = acc; pcnt[wq][lane] = cnt; }
    if (lane == 0) pden[wq] = den;
    __syncthreads();
    if (wq == 0) {
        float dens = 0.f;
#pragma unroll
        for (int q = 0; q < 8; q++) dens += pden[q];
        float dd = fmaxf(dens, 1e-8f);
        float accs = 0.f; int cnts = -1;
        if (lane < Cc) {
            accs = 0.f; cnts = 0;
#pragma unroll
            for (int q = 0; q < 8; q++) { accs += pacc[q][lane]; cnts += pcnt[q][lane]; }
            float val = accs / dd;
            g_splabel[gw*Cc + lane] = val;
            splabT_out[(size_t)b*Cc*Mm + lane*Mm + m] = val;
        }
        int v = cnts;
        int bi = lane;
        const unsigned mask = 0xffffffffu;
#pragma unroll
        for (int off = 16; off > 0; off >>= 1) {
            int ov = __shfl_down_sync(mask, v, off);
            int oi = __shfl_down_sync(mask, bi, off);
            if (ov > v || (ov == v && oi < bi)) { v = ov; bi = oi; }
        }
        int win = __shfl_sync(mask, bi, 0);
        if (lane == 0) pseudo_out[b*Mm + m] = (float)win;
        if (lane < Cc) pseudo_oh_out[(size_t)b*Cc*Mm + lane*Mm + m] = (lane == win) ? 1.0f : 0.0f;
    }
}

// ---------------- merged final: feadist copy, argmax/re_p_xyz, re_p_label ----------------
__global__ void final13_kernel(const float* __restrict__ wfinal,
                               float* __restrict__ feadist_out, float* __restrict__ repxyz_out,
                               float* __restrict__ replabel_out) {
    int id = blockIdx.x*blockDim.x + threadIdx.x;
    int b = id / Nn;
    size_t bn = (size_t)id;
    float wv[Kk];
#pragma unroll
    for (int k = 0; k < Kk; k++) { wv[k] = wfinal[bn*Kk+k]; feadist_out[bn*Kk+k] = wv[k]; }
    int bk = 0; float bv = wv[0];
#pragma unroll
    for (int k = 1; k < Kk; k++) if (wv[k] > bv) { bv = wv[k]; bk = k; }
    int msel = g_idx[bn*Kk+bk];
#pragma unroll
    for (int j = 0; j < 3; j++) repxyz_out[bn*3+j] = g_spxyz[((size_t)b*Mm+msel)*3 + j];
    float acc[Cc];
#pragma unroll
    for (int c = 0; c < Cc; c++) acc[c] = 0.0f;
#pragma unroll
    for (int k = 0; k < Kk; k++) {
        float wt = wv[k];
        int m = g_idx[bn*Kk+k];
        const float* sl = g_splabel + ((size_t)b*Mm+m)*Cc;
#pragma unroll
        for (int c = 0; c < Cc; c++) acc[c] += wt * sl[c];
    }
#pragma unroll
    for (int c = 0; c < Cc; c++) replabel_out[bn*Cc+c] = acc[c];
}

extern "C" void kernel_launch(void* const* d_in, const int* in_sizes, int n_in,
                              void* d_out, int out_size) {
    const float* pc     = (const float*)d_in[0];
    const float* knn    = (const float*)d_in[1];
    const float* onehot = (const float*)d_in[2];
    const int*   label  = (const int*)d_in[3];
    const float* Wk1 = (const float*)d_in[4];
    const float* Wk2 = (const float*)d_in[5];
    const float* Wg  = (const float*)d_in[6];
    const float* W1  = (const float*)d_in[7];
    const float* W2  = (const float*)d_in[8];
    const float* Wf1 = (const float*)d_in[9];
    const float* Wf2 = (const float*)d_in[10];
    const float* Wx1 = (const float*)d_in[11];
    const float* Wx2 = (const float*)d_in[12];
    const float* Wm1 = (const float*)d_in[13];
    const float* Wm2 = (const float*)d_in[14];
    float* out = (float*)d_out;

    cudaFuncSetAttribute((const void*)fps_kernel,
                         cudaFuncAttributeMaxDynamicSharedMemorySize, 3*Nn*4);
    cudaFuncSetAttribute((const void*)pfea_kernel,
                         cudaFuncAttributeMaxDynamicSharedMemorySize, 12352*4);

    float* w_buf = out + OFF_FINAL_ASSO;   // final_asso region doubles as the live w buffer
    float* pfea  = out + OFF_PFEA;         // p_fea region is the canonical p_fea storage

    // Fork s2 off the capture stream FIRST (wait-event on an origin-stream event
    // is the required entry into the capture graph), then pfea runs on s2 with
    // no dependency on fps — concurrent at replay.
    cudaStream_t s2;
    cudaStreamCreateWithFlags(&s2, cudaStreamNonBlocking);
    cudaEvent_t e0, e2;
    cudaEventCreateWithFlags(&e0, cudaEventDisableTiming);
    cudaEventCreateWithFlags(&e2, cudaEventDisableTiming);

    cudaEventRecord(e0, 0);
    cudaStreamWaitEvent(s2, e0, 0);
    pfea_kernel<<<(Bb*Nn)/128, 128, 12352*4, s2>>>(pc, knn, Wk1, Wk2, Wg, W1, W2, Wm1, Wm2,
                                                   pfea, out + OFF_OUT);
    cudaEventRecord(e2, s2);

    fps_kernel<<<Bb, 1024, 3*Nn*4>>>(pc, out + OFF_CLUSTER_IDX);        // zeroes counts too
    topk_kernel<<<dim3(Nn/256, Bb), 256>>>(pc, out + OFF_C2P_ABS, out + OFF_C2P_IDX);
    scan_kernel<<<1, 1024>>>();
    fill_kernel<<<(Bb*Nn)/256, 256>>>();
    cudaStreamWaitEvent(0, e2, 0);   // scatter needs pfea
    scatter_kernel<<<Bb*Mm, 256>>>(pfea, pc, w_buf, 1, Wf1, Wx1, 0);
    for (int l = 0; l < 4; l++) {
        layer_kernel<<<(Bb*Nn)/256, 256>>>(l, pfea, pc, Wf1, Wf2, Wx1, Wx2, w_buf);
        scatter_kernel<<<Bb*Mm, 256>>>(pfea, pc, w_buf, 0, Wf1, Wx1,
                                       (l < 3) ? (l + 1) : -1);
    }
    final2_kernel<<<Bb*Mm, 256>>>(w_buf, onehot, label,
                                  out + OFF_SPLABT, out + OFF_PSEUDO, out + OFF_PSEUDO_OH);
    final13_kernel<<<(Bb*Nn)/256, 256>>>(w_buf, out + OFF_FEADIST, out + OFF_REPXYZ,
                                         out + OFF_REPLABEL);
}